// round 12
// baseline (speedup 1.0000x reference)
#include <cuda_runtime.h>
#include <cuda_fp16.h>
#include <cuda_bf16.h>

// RecSysGNN (LightGCN, 3 layers) on GB300 — R9.
// - gather tables pre-scaled by dinv[src]: CSR entry = bare int (4B), inner
//   loop = 1 SHFL + 1 LDG.128 + adds; post-scale by dinv[dst]
// - quad-processing: 8 lanes/row, 4 edges per iteration, zero-row padding
// - scatter reads no dinv (no random gather), writes 4B
// - dual fp16 outputs per layer: unscaled (for acc) + self-scaled (for gather)

#define NMAX 200000
#define EMAX 4000000
#define DIM  64

__device__ int      g_is64;
__device__ int      g_counts[NMAX];
__device__ int      g_offs[NMAX];      // block-local scan; add g_bsums[i>>10]
__device__ float    g_dinv[NMAX];
__device__ int      g_bsums[1024];
__device__ unsigned short g_rank[EMAX];
__device__ __align__(16) int   g_csr_idx[EMAX];
// fp16 tables, 8 x uint4 (=128B) per row; +1 zero row at index N for padding
__device__ uint4 g_w16s[(size_t)(NMAX + 1) * 8];
__device__ uint4 g_l1u [(size_t)NMAX * 8];
__device__ uint4 g_l1sc[(size_t)(NMAX + 1) * 8];
__device__ uint4 g_l2u [(size_t)NMAX * 8];
__device__ uint4 g_l2sc[(size_t)(NMAX + 1) * 8];

__device__ __forceinline__ unsigned pack2(float x, float y) {
    union { __half2 h; unsigned u; } c;
    c.h = __floats2half2_rn(x, y);
    return c.u;
}
__device__ __forceinline__ float2 unpack2(unsigned u) {
    union { unsigned u; __half2 h; } c;
    c.u = u;
    return __half22float2(c.h);
}

// ---------------------------------------------------------------------------
// zero counts; block 0 sniffs edge dtype (int64 values < 2^31 => hi words 0)
__global__ void k_setup(const int* __restrict__ e, int n) {
    int i = blockIdx.x * blockDim.x + threadIdx.x;
    if (i < n) g_counts[i] = 0;
    if (blockIdx.x == 0) {
        __shared__ int any;
        if (threadIdx.x == 0) any = 0;
        __syncthreads();
        int local = 0;
        for (int j = threadIdx.x; j < 2048; j += blockDim.x)
            if (e[2 * j + 1] != 0) local = 1;
        if (local) any = 1;
        __syncthreads();
        if (threadIdx.x == 0) g_is64 = (any == 0) ? 1 : 0;
    }
}

__device__ __forceinline__ int edge_at(const void* e, size_t idx, int is64) {
    if (is64) return (int)((const long long*)e)[idx];
    return ((const int*)e)[idx];
}

// count + capture per-edge rank within dst bucket (atomic return value)
__global__ void k_count(const void* __restrict__ edges, int E, int N) {
    int i = blockIdx.x * blockDim.x + threadIdx.x;
    if (i >= E) return;
    int is64 = g_is64;
    int d = edge_at(edges, (size_t)E + i, is64);
    unsigned r = 0;
    if ((unsigned)d < (unsigned)N) r = (unsigned)atomicAdd(&g_counts[d], 1);
    g_rank[i] = (unsigned short)r;
}

__device__ __forceinline__ int warp_iscan(int x, int lane) {
#pragma unroll
    for (int o = 1; o < 32; o <<= 1) {
        int y = __shfl_up_sync(0xffffffffu, x, o);
        if (lane >= o) x += y;
    }
    return x;
}

// block-local exclusive scan of counts -> offs (+ dinv); block sums -> bsums
__global__ void k_scan1(int n) {
    int tid  = threadIdx.x;
    int gid  = blockIdx.x * 1024 + tid;
    int v    = (gid < n) ? g_counts[gid] : 0;
    if (gid < n) g_dinv[gid] = (v > 0) ? rsqrtf((float)v) : 0.0f;
    int lane = tid & 31, wid = tid >> 5;
    int inc  = warp_iscan(v, lane);
    __shared__ int ws[32];
    if (lane == 31) ws[wid] = inc;
    __syncthreads();
    if (wid == 0) { int t = ws[lane]; t = warp_iscan(t, lane); ws[lane] = t; }
    __syncthreads();
    int incl = inc + (wid ? ws[wid - 1] : 0);
    if (gid < n) g_offs[gid] = incl - v;
    if (tid == 1023) g_bsums[blockIdx.x] = incl;
}

__global__ void k_scan2(int nb) {
    int tid  = threadIdx.x;
    int v    = (tid < nb) ? g_bsums[tid] : 0;
    int lane = tid & 31, wid = tid >> 5;
    int inc  = warp_iscan(v, lane);
    __shared__ int ws[32];
    if (lane == 31) ws[wid] = inc;
    __syncthreads();
    if (wid == 0) { int t = ws[lane]; t = warp_iscan(t, lane); ws[lane] = t; }
    __syncthreads();
    int incl = inc + (wid ? ws[wid - 1] : 0);
    if (tid < nb) g_bsums[tid] = incl - v;
}

// no atomics, no dinv reads: pos = offs[d]+bsums[d>>10]+rank[i]; 4B store
__global__ void k_scatter(const void* __restrict__ edges, int E, int N) {
    int i = blockIdx.x * blockDim.x + threadIdx.x;
    if (i >= E) return;
    int is64 = g_is64;
    int s = edge_at(edges, (size_t)i, is64);
    int d = edge_at(edges, (size_t)E + i, is64);
    if ((unsigned)s >= (unsigned)N || (unsigned)d >= (unsigned)N) return;
    int pos = g_offs[d] + g_bsums[d >> 10] + (int)g_rank[i];
    if ((unsigned)pos < (unsigned)EMAX) g_csr_idx[pos] = s;
}

// out[0:ND) = emb0; w16s = dinv[row]-scaled fp16 table; zero padding row at N
__global__ void k_init(const float4* __restrict__ w, float4* __restrict__ out, int N) {
    int j = blockIdx.x * blockDim.x + threadIdx.x;   // one uint4 (8 halves) each
    int total = N * 8;
    if (j < total) {
        int row = j >> 3;
        float4 v0 = w[2 * j];
        float4 v1 = w[2 * j + 1];
        out[2 * j]     = v0;
        out[2 * j + 1] = v1;
        float dv = g_dinv[row];
        uint4 p;
        p.x = pack2(v0.x * dv, v0.y * dv);
        p.y = pack2(v0.z * dv, v0.w * dv);
        p.z = pack2(v1.x * dv, v1.y * dv);
        p.w = pack2(v1.z * dv, v1.w * dv);
        g_w16s[j] = p;
    } else if (j < total + 8) {
        uint4 z = make_uint4(0, 0, 0, 0);
        int zi = j - total;
        g_w16s[(size_t)N * 8 + zi] = z;
        g_l1sc[(size_t)N * 8 + zi] = z;
        g_l2sc[(size_t)N * 8 + zi] = z;
    }
}

// One warp per dst node. 8 lanes per row (lane&7 = dim group of 8),
// lane>>3 in {0..3} = edge subgroup: 4 edges per inner iteration.
__device__ __forceinline__ void gather4(const uint4* __restrict__ prev,
                                        int start, int cnt, int lane, int zrow,
                                        float a[8]) {
    int sub = lane & 7;
    int h   = lane >> 3;
    for (int b = 0; b < cnt; b += 32) {
        int j = b + lane;
        int s = (j < cnt) ? g_csr_idx[start + j] : zrow;   // zero row pads
        int m     = min(32, cnt - b);
        int iters = (m + 3) >> 2;
#pragma unroll 4
        for (int k = 0; k < iters; k++) {
            int ss = __shfl_sync(0xffffffffu, s, 4 * k + h);
            uint4 dv = prev[ss * 8 + sub];
            float2 e;
            e = unpack2(dv.x); a[0] += e.x; a[1] += e.y;
            e = unpack2(dv.y); a[2] += e.x; a[3] += e.y;
            e = unpack2(dv.z); a[4] += e.x; a[5] += e.y;
            e = unpack2(dv.w); a[6] += e.x; a[7] += e.y;
        }
    }
#pragma unroll
    for (int o = 8; o <= 16; o <<= 1)
#pragma unroll
        for (int i = 0; i < 8; i++)
            a[i] += __shfl_xor_sync(0xffffffffu, a[i], o);
}

__device__ __forceinline__ int node_start(int node) {
    return g_offs[node] + g_bsums[node >> 10];
}

__device__ __forceinline__ uint4 pack8(const float a[8], float sc) {
    uint4 p;
    p.x = pack2(a[0] * sc, a[1] * sc);
    p.y = pack2(a[2] * sc, a[3] * sc);
    p.z = pack2(a[4] * sc, a[5] * sc);
    p.w = pack2(a[6] * sc, a[7] * sc);
    return p;
}

__global__ void k_prop0(int N) {
    int warp = (blockIdx.x * blockDim.x + threadIdx.x) >> 5;
    int lane = threadIdx.x & 31;
    if (warp >= N) return;
    float a[8] = {0, 0, 0, 0, 0, 0, 0, 0};
    gather4(g_w16s, node_start(warp), g_counts[warp], lane, N, a);
    if (lane < 8) {
        float dv = g_dinv[warp];
        size_t idx = (size_t)warp * 8 + lane;
        g_l1u[idx]  = pack8(a, dv);        // unscaled l1 (for acc)
        g_l1sc[idx] = pack8(a, dv * dv);   // dinv-scaled (for next gather)
    }
}

__global__ void k_prop1(int N) {
    int warp = (blockIdx.x * blockDim.x + threadIdx.x) >> 5;
    int lane = threadIdx.x & 31;
    if (warp >= N) return;
    float a[8] = {0, 0, 0, 0, 0, 0, 0, 0};
    gather4(g_l1sc, node_start(warp), g_counts[warp], lane, N, a);
    if (lane < 8) {
        float dv = g_dinv[warp];
        size_t idx = (size_t)warp * 8 + lane;
        g_l2u[idx]  = pack8(a, dv);
        g_l2sc[idx] = pack8(a, dv * dv);
    }
}

// final: acc = 0.25 * (emb0 + l1 + l2 + l3), two float4 stores per lane<8
__global__ void k_prop2(const float4* __restrict__ w4, float4* __restrict__ acc, int N) {
    int warp = (blockIdx.x * blockDim.x + threadIdx.x) >> 5;
    int lane = threadIdx.x & 31;
    if (warp >= N) return;
    float a[8] = {0, 0, 0, 0, 0, 0, 0, 0};
    gather4(g_l2sc, node_start(warp), g_counts[warp], lane, N, a);
    if (lane < 8) {
        float dv = g_dinv[warp];
        size_t idx = (size_t)warp * 8 + lane;
        float4 e0a = w4[2 * idx];
        float4 e0b = w4[2 * idx + 1];
        uint4 u1 = g_l1u[idx];
        uint4 u2 = g_l2u[idx];
        float2 p1, p2;
        float4 r;
        p1 = unpack2(u1.x); p2 = unpack2(u2.x);
        r.x = (e0a.x + p1.x + p2.x + a[0] * dv) * 0.25f;
        r.y = (e0a.y + p1.y + p2.y + a[1] * dv) * 0.25f;
        p1 = unpack2(u1.y); p2 = unpack2(u2.y);
        r.z = (e0a.z + p1.x + p2.x + a[2] * dv) * 0.25f;
        r.w = (e0a.w + p1.y + p2.y + a[3] * dv) * 0.25f;
        acc[2 * idx] = r;
        p1 = unpack2(u1.z); p2 = unpack2(u2.z);
        r.x = (e0b.x + p1.x + p2.x + a[4] * dv) * 0.25f;
        r.y = (e0b.y + p1.y + p2.y + a[5] * dv) * 0.25f;
        p1 = unpack2(u1.w); p2 = unpack2(u2.w);
        r.z = (e0b.z + p1.x + p2.x + a[6] * dv) * 0.25f;
        r.w = (e0b.w + p1.y + p2.y + a[7] * dv) * 0.25f;
        acc[2 * idx + 1] = r;
    }
}

// ---------------------------------------------------------------------------
extern "C" void kernel_launch(void* const* d_in, const int* in_sizes, int n_in,
                              void* d_out, int out_size) {
    const void*  edges = d_in[0];                 // [2, E] int32 or int64
    const float* w     = (const float*)d_in[1];   // float32 [N, D]
    int E = in_sizes[0] / 2;
    int N = in_sizes[1] / DIM;
    float* out = (float*)d_out;

    const int TB = 256;
    k_setup<<<(N + TB - 1) / TB, TB>>>((const int*)edges, N);
    k_count<<<(E + TB - 1) / TB, TB>>>(edges, E, N);

    int nb = (N + 1023) / 1024;
    k_scan1<<<nb, 1024>>>(N);
    k_scan2<<<1, 1024>>>(nb);

    k_scatter<<<(E + TB - 1) / TB, TB>>>(edges, E, N);

    int ninit = N * 8 + 8;
    k_init<<<(ninit + TB - 1) / TB, TB>>>((const float4*)w, (float4*)out, N);

    float4* acc = (float4*)(out + (size_t)N * DIM);
    int pgrid = (int)(((long long)N * 32 + TB - 1) / TB);
    k_prop0<<<pgrid, TB>>>(N);
    k_prop1<<<pgrid, TB>>>(N);
    k_prop2<<<pgrid, TB>>>((const float4*)w, acc, N);
}